// round 10
// baseline (speedup 1.0000x reference)
#include <cuda_runtime.h>
#include <cstdint>
#include <math.h>

#define B_  4
#define N_  2048
#define D_  1024
#define H_  16
#define DH_ 64

// Scratch: projected Q/K/V in [B*H][N][dh] layout, attention output X in [B*N][D]
__device__ float g_Q[B_ * H_ * N_ * DH_];
__device__ float g_K[B_ * H_ * N_ * DH_];
__device__ float g_V[B_ * H_ * N_ * DH_];
__device__ float g_X[B_ * N_ * D_];

__device__ __forceinline__ uint32_t f2tf32(float x) {
    uint32_t r;
    asm("cvt.rna.tf32.f32 %0, %1;" : "=r"(r) : "f"(x));
    return r;
}
__device__ __forceinline__ float ex2f(float x) {
    float y;
    asm("ex2.approx.ftz.f32 %0, %1;" : "=f"(y) : "f"(x));
    return y;
}

__device__ __forceinline__ void mma_tf32_16x8x8(
    float& c0, float& c1, float& c2, float& c3,
    uint32_t a0, uint32_t a1, uint32_t a2, uint32_t a3,
    uint32_t b0, uint32_t b1)
{
    asm volatile(
        "mma.sync.aligned.m16n8k8.row.col.f32.tf32.tf32.f32 "
        "{%0,%1,%2,%3}, {%4,%5,%6,%7}, {%8,%9}, {%0,%1,%2,%3};"
        : "+f"(c0), "+f"(c1), "+f"(c2), "+f"(c3)
        : "r"(a0), "r"(a1), "r"(a2), "r"(a3), "r"(b0), "r"(b1));
}

#define LDSM4(r0, r1, r2, r3, addr) \
    asm volatile("ldmatrix.sync.aligned.m8n8.x4.shared.b16 {%0,%1,%2,%3}, [%4];" \
                 : "=r"(r0), "=r"(r1), "=r"(r2), "=r"(r3) : "r"(addr))

// ===========================================================================
// tf32 mma.sync GEMM: C[M,1024] = A[M,1024] @ W^T (+bias), W row-major [N][K].
// CTA tile 128x128, k-tile 32. 8 warps (4 m x 2 n), warp tile 32x64.
// R9 structure + LDSM fragment loads (6 ldmatrix.x4 per k-block vs 24 LDS32),
// double-buffered fragments across the 4 k-blocks.
// ===========================================================================
#define KSTR 36   // padded k stride in uint32 (144 B rows, 16B-aligned)

template <bool OUT_HEADS, bool HAS_BIAS>
__device__ __forceinline__ void gemm_mma_body(
    const float* __restrict__ A, const float* __restrict__ W,
    const float* __restrict__ bias, float* __restrict__ out)
{
    __shared__ uint32_t As[128 * KSTR];
    __shared__ uint32_t Bs[128 * KSTR];

    const int tid  = threadIdx.x;
    const int wid  = tid >> 5;
    const int lane = tid & 31;
    const int g    = lane >> 2;
    const int tig  = lane & 3;
    const int wm   = wid & 3;
    const int wn   = wid >> 2;
    const int m0   = blockIdx.y * 128;
    const int n0   = blockIdx.x * 128;

    float c[2][8][4];
#pragma unroll
    for (int t = 0; t < 2; t++)
#pragma unroll
        for (int j = 0; j < 8; j++)
#pragma unroll
            for (int e = 0; e < 4; e++) c[t][j][e] = 0.f;

    // ldmatrix per-lane addresses (affine: +32B per k-block)
    // A tile t: d0 rows R..R+7 @kk, d1 rows R+8..R+15 @kk, d2/d3 same @kk+4
    //   lane -> row = R + (lane&15), col32 = (lane&16) ? 4 : 0
    // B pair p (j = 2p, 2p+1): d0 (j=2p,@kk), d1 (j=2p,@kk+4),
    //                           d2 (j=2p+1,@kk), d3 (j=2p+1,@kk+4)
    //   lane -> row = wn*64 + p*16 + (lane&7) + ((lane&16)?8:0),
    //           col32 = (lane&8) ? 4 : 0
    const uint32_t as_base = (uint32_t)__cvta_generic_to_shared(As);
    const uint32_t bs_base = (uint32_t)__cvta_generic_to_shared(Bs);
    uint32_t a_addr[2], b_addr[4];
#pragma unroll
    for (int t = 0; t < 2; t++)
        a_addr[t] = as_base +
            (((uint32_t)(wm * 32 + t * 16 + (lane & 15)) * KSTR) +
             ((lane & 16) ? 4u : 0u)) * 4u;
#pragma unroll
    for (int p = 0; p < 4; p++)
        b_addr[p] = bs_base +
            (((uint32_t)(wn * 64 + p * 16 + (lane & 7) + ((lane & 16) ? 8 : 0)) * KSTR) +
             ((lane & 8) ? 4u : 0u)) * 4u;

    for (int kt = 0; kt < D_; kt += 32) {
        // Producer: load 128x32 tiles of A and W, convert to tf32, store padded.
#pragma unroll
        for (int u = 0; u < 4; u++) {
            int f   = tid + 256 * u;
            int row = f >> 3;
            int q   = f & 7;
            float4 av = __ldg((const float4*)(A + (size_t)(m0 + row) * D_ + kt + q * 4));
            uint4 at;
            at.x = f2tf32(av.x); at.y = f2tf32(av.y);
            at.z = f2tf32(av.z); at.w = f2tf32(av.w);
            *(uint4*)&As[row * KSTR + q * 4] = at;
            float4 wv = __ldg((const float4*)(W + (size_t)(n0 + row) * D_ + kt + q * 4));
            uint4 wt;
            wt.x = f2tf32(wv.x); wt.y = f2tf32(wv.y);
            wt.z = f2tf32(wv.z); wt.w = f2tf32(wv.w);
            *(uint4*)&Bs[row * KSTR + q * 4] = wt;
        }
        __syncthreads();

        // Consumer: LDSM fragments, double-buffered across the 4 k-blocks.
        uint32_t a[2][2][4];   // [buf][m-tile][elem]
        uint32_t b[2][8][2];   // [buf][n-tile][elem]

        // preload k-block 0 into buf 0
        LDSM4(a[0][0][0], a[0][0][1], a[0][0][2], a[0][0][3], a_addr[0]);
        LDSM4(a[0][1][0], a[0][1][1], a[0][1][2], a[0][1][3], a_addr[1]);
#pragma unroll
        for (int p = 0; p < 4; p++)
            LDSM4(b[0][2 * p][0], b[0][2 * p][1],
                  b[0][2 * p + 1][0], b[0][2 * p + 1][1], b_addr[p]);

#pragma unroll
        for (int kb = 0; kb < 4; kb++) {
            const int cur = kb & 1;
            const int nxt = cur ^ 1;
            if (kb < 3) {
                const uint32_t off = (uint32_t)(kb + 1) * 32u;   // 8 floats
                LDSM4(a[nxt][0][0], a[nxt][0][1], a[nxt][0][2], a[nxt][0][3],
                      a_addr[0] + off);
                LDSM4(a[nxt][1][0], a[nxt][1][1], a[nxt][1][2], a[nxt][1][3],
                      a_addr[1] + off);
#pragma unroll
                for (int p = 0; p < 4; p++)
                    LDSM4(b[nxt][2 * p][0], b[nxt][2 * p][1],
                          b[nxt][2 * p + 1][0], b[nxt][2 * p + 1][1],
                          b_addr[p] + off);
            }
#pragma unroll
            for (int t = 0; t < 2; t++)
#pragma unroll
                for (int j = 0; j < 8; j++)
                    mma_tf32_16x8x8(c[t][j][0], c[t][j][1], c[t][j][2], c[t][j][3],
                                    a[cur][t][0], a[cur][t][1], a[cur][t][2], a[cur][t][3],
                                    b[cur][j][0], b[cur][j][1]);
        }
        __syncthreads();
    }

    // Epilogue (unchanged)
#pragma unroll
    for (int t = 0; t < 2; t++) {
        const int r0 = m0 + wm * 32 + t * 16 + g;
#pragma unroll
        for (int j = 0; j < 8; j++) {
            const int col = n0 + wn * 64 + j * 8 + tig * 2;
            float2 v0 = make_float2(c[t][j][0], c[t][j][1]);
            float2 v1 = make_float2(c[t][j][2], c[t][j][3]);
            if (HAS_BIAS) {
                float2 bv = *(const float2*)(bias + col);
                v0.x += bv.x; v0.y += bv.y;
                v1.x += bv.x; v1.y += bv.y;
            }
            if (OUT_HEADS) {
                const int h = col >> 6;
                const int di = col & 63;
                const int b0i = r0 >> 11, n0i = r0 & 2047;
                const int r1 = r0 + 8;
                const int b1i = r1 >> 11, n1i = r1 & 2047;
                *(float2*)(out + (((size_t)(b0i * H_ + h)) * N_ + n0i) * DH_ + di) = v0;
                *(float2*)(out + (((size_t)(b1i * H_ + h)) * N_ + n1i) * DH_ + di) = v1;
            } else {
                *(float2*)(out + (size_t)r0 * D_ + col) = v0;
                *(float2*)(out + (size_t)(r0 + 8) * D_ + col) = v1;
            }
        }
    }
}

__global__ __launch_bounds__(256, 2)
void proj_qkv_mma(const float* __restrict__ xq, const float* __restrict__ xk,
                  const float* __restrict__ xv,
                  const float* __restrict__ Wq, const float* __restrict__ bq,
                  const float* __restrict__ Wk, const float* __restrict__ bk,
                  const float* __restrict__ Wv, const float* __restrict__ bv)
{
    int z = blockIdx.z;
    const float* A = (z == 0) ? xq : (z == 1) ? xk : xv;
    const float* W = (z == 0) ? Wq : (z == 1) ? Wk : Wv;
    const float* b = (z == 0) ? bq : (z == 1) ? bk : bv;
    float* out = (z == 0) ? g_Q : (z == 1) ? g_K : g_V;
    gemm_mma_body<true, true>(A, W, b, out);
}

__global__ __launch_bounds__(256, 2)
void proj_out_mma(const float* __restrict__ Wo, float* __restrict__ out)
{
    gemm_mma_body<false, false>(g_X, Wo, nullptr, out);
}

// ===========================================================================
// Tensor-core flash attention (tf32 mma.sync), causal, dh=64.
// CTA: 128 threads (4 warps). 64-query tile (proven R9 version, unchanged).
// ===========================================================================
#define QSTR 68
#define VSTR 72
#define FL_SMEM ((64 * QSTR * 2 + 64 * VSTR) * 4)

__global__ __launch_bounds__(128, 4) void flash_mma_kernel()
{
    extern __shared__ uint32_t fsm[];
    uint32_t* Qs = fsm;                 // [64][QSTR]
    uint32_t* Ks = Qs + 64 * QSTR;      // [64][QSTR]
    uint32_t* Vs = Ks + 64 * QSTR;      // [64][VSTR]

    const int tid  = threadIdx.x;
    const int wq   = tid >> 5;
    const int lane = tid & 31;
    const int g    = lane >> 2;
    const int tig  = lane & 3;
    const int qt   = gridDim.x - 1 - blockIdx.x;
    const int bh   = blockIdx.y;
    const int qi0  = qt * 64;

    const float* Qg = g_Q + (size_t)bh * N_ * DH_;
    const float* Kg = g_K + (size_t)bh * N_ * DH_;
    const float* Vg = g_V + (size_t)bh * N_ * DH_;

    const float qscale = 0.125f * 1.44269504088896340736f;

#pragma unroll
    for (int u = 0; u < 8; u++) {
        int f  = tid + 128 * u;
        int r  = f >> 4;
        int dv = f & 15;
        float4 v = *(const float4*)(Qg + (size_t)(qi0 + r) * DH_ + dv * 4);
        uint4 t;
        t.x = f2tf32(v.x * qscale); t.y = f2tf32(v.y * qscale);
        t.z = f2tf32(v.z * qscale); t.w = f2tf32(v.w * qscale);
        *(uint4*)&Qs[r * QSTR + dv * 4] = t;
    }

    float m0r = -1e30f, m1r = -1e30f;
    float l0r = 0.f, l1r = 0.f;
    float O[8][4];
#pragma unroll
    for (int j = 0; j < 8; j++)
#pragma unroll
        for (int e = 0; e < 4; e++) O[j][e] = 0.f;

    const int row0 = qi0 + wq * 16 + g;
    const int row1 = row0 + 8;

    for (int kt2 = 0; kt2 <= qt; kt2++) {
        const int kj0 = kt2 * 64;
        __syncthreads();

#pragma unroll
        for (int u = 0; u < 8; u++) {
            int f  = tid + 128 * u;
            int r  = f >> 4;
            int dv = f & 15;
            float4 kv = *(const float4*)(Kg + (size_t)(kj0 + r) * DH_ + dv * 4);
            uint4 kt_;
            kt_.x = f2tf32(kv.x); kt_.y = f2tf32(kv.y);
            kt_.z = f2tf32(kv.z); kt_.w = f2tf32(kv.w);
            *(uint4*)&Ks[r * QSTR + dv * 4] = kt_;
            float4 vv = *(const float4*)(Vg + (size_t)(kj0 + r) * DH_ + dv * 4);
            uint4 vt;
            vt.x = f2tf32(vv.x); vt.y = f2tf32(vv.y);
            vt.z = f2tf32(vv.z); vt.w = f2tf32(vv.w);
            *(uint4*)&Vs[r * VSTR + dv * 4] = vt;
        }
        __syncthreads();

        float S[8][4];
#pragma unroll
        for (int j = 0; j < 8; j++)
#pragma unroll
            for (int e = 0; e < 4; e++) S[j][e] = 0.f;

#pragma unroll
        for (int kb = 0; kb < 8; kb++) {
            const int ar = (wq * 16 + g) * QSTR + kb * 8 + tig;
            uint32_t a0 = Qs[ar];
            uint32_t a1 = Qs[ar + 8 * QSTR];
            uint32_t a2 = Qs[ar + 4];
            uint32_t a3 = Qs[ar + 8 * QSTR + 4];
#pragma unroll
            for (int j = 0; j < 8; j++) {
                const int br = (j * 8 + g) * QSTR + kb * 8 + tig;
                uint32_t b0 = Ks[br];
                uint32_t b1 = Ks[br + 4];
                mma_tf32_16x8x8(S[j][0], S[j][1], S[j][2], S[j][3],
                                a0, a1, a2, a3, b0, b1);
            }
        }

        if (kt2 == qt) {
#pragma unroll
            for (int j = 0; j < 8; j++) {
                int c = kj0 + j * 8 + tig * 2;
                if (c     > row0) S[j][0] = -1e30f;
                if (c + 1 > row0) S[j][1] = -1e30f;
                if (c     > row1) S[j][2] = -1e30f;
                if (c + 1 > row1) S[j][3] = -1e30f;
            }
        }

        float rmax0 = -1e30f, rmax1 = -1e30f;
#pragma unroll
        for (int j = 0; j < 8; j++) {
            rmax0 = fmaxf(rmax0, fmaxf(S[j][0], S[j][1]));
            rmax1 = fmaxf(rmax1, fmaxf(S[j][2], S[j][3]));
        }
        rmax0 = fmaxf(rmax0, __shfl_xor_sync(0xffffffffu, rmax0, 1));
        rmax0 = fmaxf(rmax0, __shfl_xor_sync(0xffffffffu, rmax0, 2));
        rmax1 = fmaxf(rmax1, __shfl_xor_sync(0xffffffffu, rmax1, 1));
        rmax1 = fmaxf(rmax1, __shfl_xor_sync(0xffffffffu, rmax1, 2));

        float mn0 = fmaxf(m0r, rmax0);
        float mn1 = fmaxf(m1r, rmax1);
        float al0 = ex2f(m0r - mn0);
        float al1 = ex2f(m1r - mn1);
        m0r = mn0; m1r = mn1;

        float sum0 = 0.f, sum1 = 0.f;
        uint32_t P[8][4];
#pragma unroll
        for (int j = 0; j < 8; j++) {
            float p0 = ex2f(S[j][0] - mn0);
            float p1 = ex2f(S[j][1] - mn0);
            float p2 = ex2f(S[j][2] - mn1);
            float p3 = ex2f(S[j][3] - mn1);
            sum0 += p0 + p1;
            sum1 += p2 + p3;
            P[j][0] = f2tf32(p0); P[j][1] = f2tf32(p1);
            P[j][2] = f2tf32(p2); P[j][3] = f2tf32(p3);
        }
        sum0 += __shfl_xor_sync(0xffffffffu, sum0, 1);
        sum0 += __shfl_xor_sync(0xffffffffu, sum0, 2);
        sum1 += __shfl_xor_sync(0xffffffffu, sum1, 1);
        sum1 += __shfl_xor_sync(0xffffffffu, sum1, 2);
        l0r = l0r * al0 + sum0;
        l1r = l1r * al1 + sum1;

#pragma unroll
        for (int j = 0; j < 8; j++) {
            O[j][0] *= al0; O[j][1] *= al0;
            O[j][2] *= al1; O[j][3] *= al1;
        }

        const int srcA = (lane & ~3) | (tig >> 1);
        const int srcB = srcA + 2;
        const bool oddc = (tig & 1);
#pragma unroll
        for (int kb = 0; kb < 8; kb++) {
            uint32_t v0 = __shfl_sync(0xffffffffu, P[kb][0], srcA);
            uint32_t v1 = __shfl_sync(0xffffffffu, P[kb][1], srcA);
            uint32_t a0 = oddc ? v1 : v0;
            uint32_t w0 = __shfl_sync(0xffffffffu, P[kb][0], srcB);
            uint32_t w1 = __shfl_sync(0xffffffffu, P[kb][1], srcB);
            uint32_t a2 = oddc ? w1 : w0;
            uint32_t x0 = __shfl_sync(0xffffffffu, P[kb][2], srcA);
            uint32_t x1 = __shfl_sync(0xffffffffu, P[kb][3], srcA);
            uint32_t a1 = oddc ? x1 : x0;
            uint32_t y0 = __shfl_sync(0xffffffffu, P[kb][2], srcB);
            uint32_t y1 = __shfl_sync(0xffffffffu, P[kb][3], srcB);
            uint32_t a3 = oddc ? y1 : y0;
#pragma unroll
            for (int j = 0; j < 8; j++) {
                uint32_t b0 = Vs[(kb * 8 + tig) * VSTR + j * 8 + g];
                uint32_t b1 = Vs[(kb * 8 + tig + 4) * VSTR + j * 8 + g];
                mma_tf32_16x8x8(O[j][0], O[j][1], O[j][2], O[j][3],
                                a0, a1, a2, a3, b0, b1);
            }
        }
    }

    const int b = bh >> 4;
    const int h = bh & 15;
    const float il0 = 1.f / l0r;
    const float il1 = 1.f / l1r;
    float* X0 = g_X + ((size_t)b * N_ + row0) * D_ + h * DH_;
    float* X1 = g_X + ((size_t)b * N_ + row1) * D_ + h * DH_;
#pragma unroll
    for (int j = 0; j < 8; j++) {
        int e = j * 8 + tig * 2;
        *(float2*)(X0 + e) = make_float2(O[j][0] * il0, O[j][1] * il0);
        *(float2*)(X1 + e) = make_float2(O[j][2] * il1, O[j][3] * il1);
    }
}

// ---------------------------------------------------------------------------
extern "C" void kernel_launch(void* const* d_in, const int* in_sizes, int n_in,
                              void* d_out, int out_size)
{
    const float* q  = (const float*)d_in[0];
    const float* k  = (const float*)d_in[1];
    const float* v  = (const float*)d_in[2];
    const float* Wq = (const float*)d_in[3];
    const float* bq = (const float*)d_in[4];
    const float* Wk = (const float*)d_in[5];
    const float* bk = (const float*)d_in[6];
    const float* Wv = (const float*)d_in[7];
    const float* bv = (const float*)d_in[8];
    const float* Wo = (const float*)d_in[9];
    float* out = (float*)d_out;

    cudaFuncSetAttribute(flash_mma_kernel, cudaFuncAttributeMaxDynamicSharedMemorySize,
                         FL_SMEM);

    // QKV projections: M=8192 -> 64 row-tiles, N=1024 -> 8 col-tiles, z = q/k/v
    dim3 gp(8, 64, 3);
    proj_qkv_mma<<<gp, 256>>>(q, k, v, Wq, bq, Wk, bk, Wv, bv);

    // Flash attention: 32 q-tiles x 64 (b,h) pairs
    dim3 gf(N_ / 64, B_ * H_);
    flash_mma_kernel<<<gf, 128, FL_SMEM>>>();

    // Output projection
    dim3 go(8, 64, 1);
    proj_out_mma<<<go, 256>>>(Wo, out);
}

// round 12
// speedup vs baseline: 1.2236x; 1.2236x over previous
#include <cuda_runtime.h>
#include <cuda_fp16.h>
#include <cstdint>
#include <math.h>

#define B_  4
#define N_  2048
#define D_  1024
#define H_  16
#define DH_ 64

// Scratch: projected Q/K/V in [B*H][N][dh] layout, attention output X in [B*N][D]
__device__ float g_Q[B_ * H_ * N_ * DH_];
__device__ float g_K[B_ * H_ * N_ * DH_];
__device__ float g_V[B_ * H_ * N_ * DH_];
__device__ float g_X[B_ * N_ * D_];

__device__ __forceinline__ uint32_t f2tf32(float x) {
    uint32_t r;
    asm("cvt.rna.tf32.f32 %0, %1;" : "=r"(r) : "f"(x));
    return r;
}
__device__ __forceinline__ float ex2f(float x) {
    float y;
    asm("ex2.approx.ftz.f32 %0, %1;" : "=f"(y) : "f"(x));
    return y;
}
// pack two f32 -> f16x2 (lo = x, hi = y), round-to-nearest
__device__ __forceinline__ uint32_t h2pack(float x, float y) {
    uint32_t r;
    asm("cvt.rn.f16x2.f32 %0, %1, %2;" : "=r"(r) : "f"(y), "f"(x));
    return r;
}

__device__ __forceinline__ void mma_tf32_16x8x8(
    float& c0, float& c1, float& c2, float& c3,
    uint32_t a0, uint32_t a1, uint32_t a2, uint32_t a3,
    uint32_t b0, uint32_t b1)
{
    asm volatile(
        "mma.sync.aligned.m16n8k8.row.col.f32.tf32.tf32.f32 "
        "{%0,%1,%2,%3}, {%4,%5,%6,%7}, {%8,%9}, {%0,%1,%2,%3};"
        : "+f"(c0), "+f"(c1), "+f"(c2), "+f"(c3)
        : "r"(a0), "r"(a1), "r"(a2), "r"(a3), "r"(b0), "r"(b1));
}

__device__ __forceinline__ void mma_f16_16x8x16(
    float& c0, float& c1, float& c2, float& c3,
    uint32_t a0, uint32_t a1, uint32_t a2, uint32_t a3,
    uint32_t b0, uint32_t b1)
{
    asm volatile(
        "mma.sync.aligned.m16n8k16.row.col.f32.f16.f16.f32 "
        "{%0,%1,%2,%3}, {%4,%5,%6,%7}, {%8,%9}, {%0,%1,%2,%3};"
        : "+f"(c0), "+f"(c1), "+f"(c2), "+f"(c3)
        : "r"(a0), "r"(a1), "r"(a2), "r"(a3), "r"(b0), "r"(b1));
}

// ===========================================================================
// fp16 mma.sync GEMM: C[M,1024] = A[M,1024] @ W^T (+bias f32), W [N][K].
// CTA tile 128x128, k-tile 32 (= 2 k16-blocks). 8 warps (4m x 2n), warp 32x64.
// Smem: half2-along-k, [row][KP=20 uint32] (16 data + 4 pad):
//   fragment reads rows g -> banks 20g+tig all distinct (conflict-free);
//   producer STS.64 phases pair rows R,R+4 -> exact 32-bank coverage.
// Fragment double-buffer across the 2 k-blocks (R9-proven pattern).
// ===========================================================================
#define KP 20   // uint32 (half2) stride per row

template <bool OUT_HEADS, bool HAS_BIAS>
__device__ __forceinline__ void gemm_mma_body(
    const float* __restrict__ A, const float* __restrict__ W,
    const float* __restrict__ bias, float* __restrict__ out)
{
    __shared__ uint32_t As[128 * KP];
    __shared__ uint32_t Bs[128 * KP];

    const int tid  = threadIdx.x;
    const int wid  = tid >> 5;
    const int lane = tid & 31;
    const int g    = lane >> 2;
    const int tig  = lane & 3;
    const int wm   = wid & 3;
    const int wn   = wid >> 2;
    const int m0   = blockIdx.y * 128;
    const int n0   = blockIdx.x * 128;

    float c[2][8][4];
#pragma unroll
    for (int t = 0; t < 2; t++)
#pragma unroll
        for (int j = 0; j < 8; j++)
#pragma unroll
            for (int e = 0; e < 4; e++) c[t][j][e] = 0.f;

    // fragment base indices
    const int ar0 = (wm * 32 + g) * KP + tig;   // + t*16*KP + kb*8 ; a1:+8*KP, a2:+4
    const int br0 = (wn * 64 + g) * KP + tig;   // + j*8*KP  + kb*8 ; b1:+4

    for (int kt = 0; kt < D_; kt += 32) {
        // Producer: 1024 uint2 slots per matrix, 4 per thread; row permutation
        // pairs rows (R, R+4) within each 16-lane STS phase for full bank coverage.
#pragma unroll
        for (int u = 0; u < 4; u++) {
            int f    = tid + 256 * u;
            int j    = f & 7;                     // uint2 col (floats 4j..4j+3)
            int rblk = f >> 3;
            int row  = (rblk & ~7) | ((rblk & 1) << 2) | ((rblk & 7) >> 1);
            float4 av = __ldg((const float4*)(A + (size_t)(m0 + row) * D_ + kt + j * 4));
            *(uint2*)&As[row * KP + 2 * j] =
                make_uint2(h2pack(av.x, av.y), h2pack(av.z, av.w));
            float4 wv = __ldg((const float4*)(W + (size_t)(n0 + row) * D_ + kt + j * 4));
            *(uint2*)&Bs[row * KP + 2 * j] =
                make_uint2(h2pack(wv.x, wv.y), h2pack(wv.z, wv.w));
        }
        __syncthreads();

        // Consumer: double-buffered fragments across the 2 k16-blocks.
        uint32_t a[2][2][4];   // [buf][m-tile][elem]
        uint32_t b[2][8][2];   // [buf][n-tile][elem]

        // preload k-block 0 into buf 0
#pragma unroll
        for (int t = 0; t < 2; t++) {
            int r = ar0 + t * 16 * KP;
            a[0][t][0] = As[r];
            a[0][t][1] = As[r + 8 * KP];
            a[0][t][2] = As[r + 4];
            a[0][t][3] = As[r + 8 * KP + 4];
        }
#pragma unroll
        for (int j = 0; j < 8; j++) {
            int r = br0 + j * 8 * KP;
            b[0][j][0] = Bs[r];
            b[0][j][1] = Bs[r + 4];
        }

#pragma unroll
        for (int kb = 0; kb < 2; kb++) {
            const int cur = kb & 1;
            const int nxt = cur ^ 1;
            if (kb < 1) {
#pragma unroll
                for (int t = 0; t < 2; t++) {
                    int r = ar0 + t * 16 * KP + 8;
                    a[nxt][t][0] = As[r];
                    a[nxt][t][1] = As[r + 8 * KP];
                    a[nxt][t][2] = As[r + 4];
                    a[nxt][t][3] = As[r + 8 * KP + 4];
                }
#pragma unroll
                for (int j = 0; j < 8; j++) {
                    int r = br0 + j * 8 * KP + 8;
                    b[nxt][j][0] = Bs[r];
                    b[nxt][j][1] = Bs[r + 4];
                }
            }
#pragma unroll
            for (int t = 0; t < 2; t++)
#pragma unroll
                for (int j = 0; j < 8; j++)
                    mma_f16_16x8x16(c[t][j][0], c[t][j][1], c[t][j][2], c[t][j][3],
                                    a[cur][t][0], a[cur][t][1], a[cur][t][2], a[cur][t][3],
                                    b[cur][j][0], b[cur][j][1]);
        }
        __syncthreads();
    }

    // Epilogue (accumulator layout identical to tf32 m16n8k8 path)
#pragma unroll
    for (int t = 0; t < 2; t++) {
        const int r0 = m0 + wm * 32 + t * 16 + g;
#pragma unroll
        for (int j = 0; j < 8; j++) {
            const int col = n0 + wn * 64 + j * 8 + tig * 2;
            float2 v0 = make_float2(c[t][j][0], c[t][j][1]);
            float2 v1 = make_float2(c[t][j][2], c[t][j][3]);
            if (HAS_BIAS) {
                float2 bv = *(const float2*)(bias + col);
                v0.x += bv.x; v0.y += bv.y;
                v1.x += bv.x; v1.y += bv.y;
            }
            if (OUT_HEADS) {
                const int h = col >> 6;
                const int di = col & 63;
                const int b0i = r0 >> 11, n0i = r0 & 2047;
                const int r1 = r0 + 8;
                const int b1i = r1 >> 11, n1i = r1 & 2047;
                *(float2*)(out + (((size_t)(b0i * H_ + h)) * N_ + n0i) * DH_ + di) = v0;
                *(float2*)(out + (((size_t)(b1i * H_ + h)) * N_ + n1i) * DH_ + di) = v1;
            } else {
                *(float2*)(out + (size_t)r0 * D_ + col) = v0;
                *(float2*)(out + (size_t)(r0 + 8) * D_ + col) = v1;
            }
        }
    }
}

__global__ __launch_bounds__(256, 2)
void proj_qkv_mma(const float* __restrict__ xq, const float* __restrict__ xk,
                  const float* __restrict__ xv,
                  const float* __restrict__ Wq, const float* __restrict__ bq,
                  const float* __restrict__ Wk, const float* __restrict__ bk,
                  const float* __restrict__ Wv, const float* __restrict__ bv)
{
    int z = blockIdx.z;
    const float* A = (z == 0) ? xq : (z == 1) ? xk : xv;
    const float* W = (z == 0) ? Wq : (z == 1) ? Wk : Wv;
    const float* b = (z == 0) ? bq : (z == 1) ? bk : bv;
    float* out = (z == 0) ? g_Q : (z == 1) ? g_K : g_V;
    gemm_mma_body<true, true>(A, W, b, out);
}

__global__ __launch_bounds__(256, 2)
void proj_out_mma(const float* __restrict__ Wo, float* __restrict__ out)
{
    gemm_mma_body<false, false>(g_X, Wo, nullptr, out);
}

// ===========================================================================
// Tensor-core flash attention (tf32 mma.sync), causal, dh=64.
// CTA: 128 threads (4 warps). 64-query tile — byte-identical R9 version.
// ===========================================================================
#define QSTR 68
#define VSTR 72
#define FL_SMEM ((64 * QSTR * 2 + 64 * VSTR) * 4)

__global__ __launch_bounds__(128, 4) void flash_mma_kernel()
{
    extern __shared__ uint32_t fsm[];
    uint32_t* Qs = fsm;                 // [64][QSTR]
    uint32_t* Ks = Qs + 64 * QSTR;      // [64][QSTR]
    uint32_t* Vs = Ks + 64 * QSTR;      // [64][VSTR]

    const int tid  = threadIdx.x;
    const int wq   = tid >> 5;
    const int lane = tid & 31;
    const int g    = lane >> 2;
    const int tig  = lane & 3;
    const int qt   = gridDim.x - 1 - blockIdx.x;
    const int bh   = blockIdx.y;
    const int qi0  = qt * 64;

    const float* Qg = g_Q + (size_t)bh * N_ * DH_;
    const float* Kg = g_K + (size_t)bh * N_ * DH_;
    const float* Vg = g_V + (size_t)bh * N_ * DH_;

    const float qscale = 0.125f * 1.44269504088896340736f;

#pragma unroll
    for (int u = 0; u < 8; u++) {
        int f  = tid + 128 * u;
        int r  = f >> 4;
        int dv = f & 15;
        float4 v = *(const float4*)(Qg + (size_t)(qi0 + r) * DH_ + dv * 4);
        uint4 t;
        t.x = f2tf32(v.x * qscale); t.y = f2tf32(v.y * qscale);
        t.z = f2tf32(v.z * qscale); t.w = f2tf32(v.w * qscale);
        *(uint4*)&Qs[r * QSTR + dv * 4] = t;
    }

    float m0r = -1e30f, m1r = -1e30f;
    float l0r = 0.f, l1r = 0.f;
    float O[8][4];
#pragma unroll
    for (int j = 0; j < 8; j++)
#pragma unroll
        for (int e = 0; e < 4; e++) O[j][e] = 0.f;

    const int row0 = qi0 + wq * 16 + g;
    const int row1 = row0 + 8;

    for (int kt2 = 0; kt2 <= qt; kt2++) {
        const int kj0 = kt2 * 64;
        __syncthreads();

#pragma unroll
        for (int u = 0; u < 8; u++) {
            int f  = tid + 128 * u;
            int r  = f >> 4;
            int dv = f & 15;
            float4 kv = *(const float4*)(Kg + (size_t)(kj0 + r) * DH_ + dv * 4);
            uint4 kt_;
            kt_.x = f2tf32(kv.x); kt_.y = f2tf32(kv.y);
            kt_.z = f2tf32(kv.z); kt_.w = f2tf32(kv.w);
            *(uint4*)&Ks[r * QSTR + dv * 4] = kt_;
            float4 vv = *(const float4*)(Vg + (size_t)(kj0 + r) * DH_ + dv * 4);
            uint4 vt;
            vt.x = f2tf32(vv.x); vt.y = f2tf32(vv.y);
            vt.z = f2tf32(vv.z); vt.w = f2tf32(vv.w);
            *(uint4*)&Vs[r * VSTR + dv * 4] = vt;
        }
        __syncthreads();

        float S[8][4];
#pragma unroll
        for (int j = 0; j < 8; j++)
#pragma unroll
            for (int e = 0; e < 4; e++) S[j][e] = 0.f;

#pragma unroll
        for (int kb = 0; kb < 8; kb++) {
            const int ar = (wq * 16 + g) * QSTR + kb * 8 + tig;
            uint32_t a0 = Qs[ar];
            uint32_t a1 = Qs[ar + 8 * QSTR];
            uint32_t a2 = Qs[ar + 4];
            uint32_t a3 = Qs[ar + 8 * QSTR + 4];
#pragma unroll
            for (int j = 0; j < 8; j++) {
                const int br = (j * 8 + g) * QSTR + kb * 8 + tig;
                uint32_t b0 = Ks[br];
                uint32_t b1 = Ks[br + 4];
                mma_tf32_16x8x8(S[j][0], S[j][1], S[j][2], S[j][3],
                                a0, a1, a2, a3, b0, b1);
            }
        }

        if (kt2 == qt) {
#pragma unroll
            for (int j = 0; j < 8; j++) {
                int c = kj0 + j * 8 + tig * 2;
                if (c     > row0) S[j][0] = -1e30f;
                if (c + 1 > row0) S[j][1] = -1e30f;
                if (c     > row1) S[j][2] = -1e30f;
                if (c + 1 > row1) S[j][3] = -1e30f;
            }
        }

        float rmax0 = -1e30f, rmax1 = -1e30f;
#pragma unroll
        for (int j = 0; j < 8; j++) {
            rmax0 = fmaxf(rmax0, fmaxf(S[j][0], S[j][1]));
            rmax1 = fmaxf(rmax1, fmaxf(S[j][2], S[j][3]));
        }
        rmax0 = fmaxf(rmax0, __shfl_xor_sync(0xffffffffu, rmax0, 1));
        rmax0 = fmaxf(rmax0, __shfl_xor_sync(0xffffffffu, rmax0, 2));
        rmax1 = fmaxf(rmax1, __shfl_xor_sync(0xffffffffu, rmax1, 1));
        rmax1 = fmaxf(rmax1, __shfl_xor_sync(0xffffffffu, rmax1, 2));

        float mn0 = fmaxf(m0r, rmax0);
        float mn1 = fmaxf(m1r, rmax1);
        float al0 = ex2f(m0r - mn0);
        float al1 = ex2f(m1r - mn1);
        m0r = mn0; m1r = mn1;

        float sum0 = 0.f, sum1 = 0.f;
        uint32_t P[8][4];
#pragma unroll
        for (int j = 0; j < 8; j++) {
            float p0 = ex2f(S[j][0] - mn0);
            float p1 = ex2f(S[j][1] - mn0);
            float p2 = ex2f(S[j][2] - mn1);
            float p3 = ex2f(S[j][3] - mn1);
            sum0 += p0 + p1;
            sum1 += p2 + p3;
            P[j][0] = f2tf32(p0); P[j][1] = f2tf32(p1);
            P[j][2] = f2tf32(p2); P[j][3] = f2tf32(p3);
        }
        sum0 += __shfl_xor_sync(0xffffffffu, sum0, 1);
        sum0 += __shfl_xor_sync(0xffffffffu, sum0, 2);
        sum1 += __shfl_xor_sync(0xffffffffu, sum1, 1);
        sum1 += __shfl_xor_sync(0xffffffffu, sum1, 2);
        l0r = l0r * al0 + sum0;
        l1r = l1r * al1 + sum1;

#pragma unroll
        for (int j = 0; j < 8; j++) {
            O[j][0] *= al0; O[j][1] *= al0;
            O[j][2] *= al1; O[j][3] *= al1;
        }

        const int srcA = (lane & ~3) | (tig >> 1);
        const int srcB = srcA + 2;
        const bool oddc = (tig & 1);
#pragma unroll
        for (int kb = 0; kb < 8; kb++) {
            uint32_t v0 = __shfl_sync(0xffffffffu, P[kb][0], srcA);
            uint32_t v1 = __shfl_sync(0xffffffffu, P[kb][1], srcA);
            uint32_t a0 = oddc ? v1 : v0;
            uint32_t w0 = __shfl_sync(0xffffffffu, P[kb][0], srcB);
            uint32_t w1 = __shfl_sync(0xffffffffu, P[kb][1], srcB);
            uint32_t a2 = oddc ? w1 : w0;
            uint32_t x0 = __shfl_sync(0xffffffffu, P[kb][2], srcA);
            uint32_t x1 = __shfl_sync(0xffffffffu, P[kb][3], srcA);
            uint32_t a1 = oddc ? x1 : x0;
            uint32_t y0 = __shfl_sync(0xffffffffu, P[kb][2], srcB);
            uint32_t y1 = __shfl_sync(0xffffffffu, P[kb][3], srcB);
            uint32_t a3 = oddc ? y1 : y0;
#pragma unroll
            for (int j = 0; j < 8; j++) {
                uint32_t b0 = Vs[(kb * 8 + tig) * VSTR + j * 8 + g];
                uint32_t b1 = Vs[(kb * 8 + tig + 4) * VSTR + j * 8 + g];
                mma_tf32_16x8x8(O[j][0], O[j][1], O[j][2], O[j][3],
                                a0, a1, a2, a3, b0, b1);
            }
        }
    }

    const int b = bh >> 4;
    const int h = bh & 15;
    const float il0 = 1.f / l0r;
    const float il1 = 1.f / l1r;
    float* X0 = g_X + ((size_t)b * N_ + row0) * D_ + h * DH_;
    float* X1 = g_X + ((size_t)b * N_ + row1) * D_ + h * DH_;
#pragma unroll
    for (int j = 0; j < 8; j++) {
        int e = j * 8 + tig * 2;
        *(float2*)(X0 + e) = make_float2(O[j][0] * il0, O[j][1] * il0);
        *(float2*)(X1 + e) = make_float2(O[j][2] * il1, O[j][3] * il1);
    }
}

// ---------------------------------------------------------------------------
extern "C" void kernel_launch(void* const* d_in, const int* in_sizes, int n_in,
                              void* d_out, int out_size)
{
    const float* q  = (const float*)d_in[0];
    const float* k  = (const float*)d_in[1];
    const float* v  = (const float*)d_in[2];
    const float* Wq = (const float*)d_in[3];
    const float* bq = (const float*)d_in[4];
    const float* Wk = (const float*)d_in[5];
    const float* bk = (const float*)d_in[6];
    const float* Wv = (const float*)d_in[7];
    const float* bv = (const float*)d_in[8];
    const float* Wo = (const float*)d_in[9];
    float* out = (float*)d_out;

    cudaFuncSetAttribute(flash_mma_kernel, cudaFuncAttributeMaxDynamicSharedMemorySize,
                         FL_SMEM);

    // QKV projections: M=8192 -> 64 row-tiles, N=1024 -> 8 col-tiles, z = q/k/v
    dim3 gp(8, 64, 3);
    proj_qkv_mma<<<gp, 256>>>(q, k, v, Wq, bq, Wk, bk, Wv, bv);

    // Flash attention: 32 q-tiles x 64 (b,h) pairs
    dim3 gf(N_ / 64, B_ * H_);
    flash_mma_kernel<<<gf, 128, FL_SMEM>>>();

    // Output projection
    dim3 go(8, 64, 1);
    proj_out_mma<<<go, 256>>>(Wo, out);
}

// round 13
// speedup vs baseline: 1.5560x; 1.2717x over previous
#include <cuda_runtime.h>
#include <cuda_fp16.h>
#include <cstdint>
#include <math.h>

#define B_  4
#define N_  2048
#define D_  1024
#define H_  16
#define DH_ 64

// Scratch: projected Q/K/V in [B*H][N][dh] layout, attention output X in [B*N][D]
__device__ float g_Q[B_ * H_ * N_ * DH_];
__device__ float g_K[B_ * H_ * N_ * DH_];
__device__ float g_V[B_ * H_ * N_ * DH_];
__device__ float g_X[B_ * N_ * D_];

__device__ __forceinline__ float ex2f(float x) {
    float y;
    asm("ex2.approx.ftz.f32 %0, %1;" : "=f"(y) : "f"(x));
    return y;
}
// pack two f32 -> f16x2 (lo = x, hi = y), round-to-nearest
__device__ __forceinline__ uint32_t h2pack(float x, float y) {
    uint32_t r;
    asm("cvt.rn.f16x2.f32 %0, %1, %2;" : "=r"(r) : "f"(y), "f"(x));
    return r;
}

__device__ __forceinline__ void mma_f16_16x8x16(
    float& c0, float& c1, float& c2, float& c3,
    uint32_t a0, uint32_t a1, uint32_t a2, uint32_t a3,
    uint32_t b0, uint32_t b1)
{
    asm volatile(
        "mma.sync.aligned.m16n8k16.row.col.f32.f16.f16.f32 "
        "{%0,%1,%2,%3}, {%4,%5,%6,%7}, {%8,%9}, {%0,%1,%2,%3};"
        : "+f"(c0), "+f"(c1), "+f"(c2), "+f"(c3)
        : "r"(a0), "r"(a1), "r"(a2), "r"(a3), "r"(b0), "r"(b1));
}

// ===========================================================================
// fp16 mma.sync GEMM: C[M,1024] = A[M,1024] @ W^T (+bias f32), W [N][K].
// (byte-identical to the 680us R12 winner)
// ===========================================================================
#define KP 20   // uint32 (half2) stride per row

template <bool OUT_HEADS, bool HAS_BIAS>
__device__ __forceinline__ void gemm_mma_body(
    const float* __restrict__ A, const float* __restrict__ W,
    const float* __restrict__ bias, float* __restrict__ out)
{
    __shared__ uint32_t As[128 * KP];
    __shared__ uint32_t Bs[128 * KP];

    const int tid  = threadIdx.x;
    const int wid  = tid >> 5;
    const int lane = tid & 31;
    const int g    = lane >> 2;
    const int tig  = lane & 3;
    const int wm   = wid & 3;
    const int wn   = wid >> 2;
    const int m0   = blockIdx.y * 128;
    const int n0   = blockIdx.x * 128;

    float c[2][8][4];
#pragma unroll
    for (int t = 0; t < 2; t++)
#pragma unroll
        for (int j = 0; j < 8; j++)
#pragma unroll
            for (int e = 0; e < 4; e++) c[t][j][e] = 0.f;

    const int ar0 = (wm * 32 + g) * KP + tig;
    const int br0 = (wn * 64 + g) * KP + tig;

    for (int kt = 0; kt < D_; kt += 32) {
#pragma unroll
        for (int u = 0; u < 4; u++) {
            int f    = tid + 256 * u;
            int j    = f & 7;
            int rblk = f >> 3;
            int row  = (rblk & ~7) | ((rblk & 1) << 2) | ((rblk & 7) >> 1);
            float4 av = __ldg((const float4*)(A + (size_t)(m0 + row) * D_ + kt + j * 4));
            *(uint2*)&As[row * KP + 2 * j] =
                make_uint2(h2pack(av.x, av.y), h2pack(av.z, av.w));
            float4 wv = __ldg((const float4*)(W + (size_t)(n0 + row) * D_ + kt + j * 4));
            *(uint2*)&Bs[row * KP + 2 * j] =
                make_uint2(h2pack(wv.x, wv.y), h2pack(wv.z, wv.w));
        }
        __syncthreads();

        uint32_t a[2][2][4];
        uint32_t b[2][8][2];

#pragma unroll
        for (int t = 0; t < 2; t++) {
            int r = ar0 + t * 16 * KP;
            a[0][t][0] = As[r];
            a[0][t][1] = As[r + 8 * KP];
            a[0][t][2] = As[r + 4];
            a[0][t][3] = As[r + 8 * KP + 4];
        }
#pragma unroll
        for (int j = 0; j < 8; j++) {
            int r = br0 + j * 8 * KP;
            b[0][j][0] = Bs[r];
            b[0][j][1] = Bs[r + 4];
        }

#pragma unroll
        for (int kb = 0; kb < 2; kb++) {
            const int cur = kb & 1;
            const int nxt = cur ^ 1;
            if (kb < 1) {
#pragma unroll
                for (int t = 0; t < 2; t++) {
                    int r = ar0 + t * 16 * KP + 8;
                    a[nxt][t][0] = As[r];
                    a[nxt][t][1] = As[r + 8 * KP];
                    a[nxt][t][2] = As[r + 4];
                    a[nxt][t][3] = As[r + 8 * KP + 4];
                }
#pragma unroll
                for (int j = 0; j < 8; j++) {
                    int r = br0 + j * 8 * KP + 8;
                    b[nxt][j][0] = Bs[r];
                    b[nxt][j][1] = Bs[r + 4];
                }
            }
#pragma unroll
            for (int t = 0; t < 2; t++)
#pragma unroll
                for (int j = 0; j < 8; j++)
                    mma_f16_16x8x16(c[t][j][0], c[t][j][1], c[t][j][2], c[t][j][3],
                                    a[cur][t][0], a[cur][t][1], a[cur][t][2], a[cur][t][3],
                                    b[cur][j][0], b[cur][j][1]);
        }
        __syncthreads();
    }

#pragma unroll
    for (int t = 0; t < 2; t++) {
        const int r0 = m0 + wm * 32 + t * 16 + g;
#pragma unroll
        for (int j = 0; j < 8; j++) {
            const int col = n0 + wn * 64 + j * 8 + tig * 2;
            float2 v0 = make_float2(c[t][j][0], c[t][j][1]);
            float2 v1 = make_float2(c[t][j][2], c[t][j][3]);
            if (HAS_BIAS) {
                float2 bv = *(const float2*)(bias + col);
                v0.x += bv.x; v0.y += bv.y;
                v1.x += bv.x; v1.y += bv.y;
            }
            if (OUT_HEADS) {
                const int h = col >> 6;
                const int di = col & 63;
                const int b0i = r0 >> 11, n0i = r0 & 2047;
                const int r1 = r0 + 8;
                const int b1i = r1 >> 11, n1i = r1 & 2047;
                *(float2*)(out + (((size_t)(b0i * H_ + h)) * N_ + n0i) * DH_ + di) = v0;
                *(float2*)(out + (((size_t)(b1i * H_ + h)) * N_ + n1i) * DH_ + di) = v1;
            } else {
                *(float2*)(out + (size_t)r0 * D_ + col) = v0;
                *(float2*)(out + (size_t)(r0 + 8) * D_ + col) = v1;
            }
        }
    }
}

__global__ __launch_bounds__(256, 2)
void proj_qkv_mma(const float* __restrict__ xq, const float* __restrict__ xk,
                  const float* __restrict__ xv,
                  const float* __restrict__ Wq, const float* __restrict__ bq,
                  const float* __restrict__ Wk, const float* __restrict__ bk,
                  const float* __restrict__ Wv, const float* __restrict__ bv)
{
    int z = blockIdx.z;
    const float* A = (z == 0) ? xq : (z == 1) ? xk : xv;
    const float* W = (z == 0) ? Wq : (z == 1) ? Wk : Wv;
    const float* b = (z == 0) ? bq : (z == 1) ? bk : bv;
    float* out = (z == 0) ? g_Q : (z == 1) ? g_K : g_V;
    gemm_mma_body<true, true>(A, W, b, out);
}

__global__ __launch_bounds__(256, 2)
void proj_out_mma(const float* __restrict__ Wo, float* __restrict__ out)
{
    gemm_mma_body<false, false>(g_X, Wo, nullptr, out);
}

// ===========================================================================
// fp16 tensor-core flash attention, causal, dh=64.
// CTA: 128 threads (4 warps), 64-query tile. m16n8k16 for QK^T and PV.
// P->A-fragment reshape is SHUFFLE-FREE: m16n8k16 A layout == two adjacent
// m16n8k8 f32 accumulator tiles.
// Smem: Q/K half2-along-dh [64][36]; V row-pair-packed half2 [32][72].
// ===========================================================================
#define QP 36   // uint32 stride per Q/K row (32 data + 4 pad)
#define VP 72   // uint32 stride per V row-pair (64 data + 8 pad)
#define FL_SMEM ((64 * QP * 2 + 32 * VP) * 4)

__global__ __launch_bounds__(128, 4) void flash_mma_kernel()
{
    extern __shared__ uint32_t fsm[];
    uint32_t* Qs = fsm;                 // [64][QP]
    uint32_t* Ks = Qs + 64 * QP;        // [64][QP]
    uint32_t* Vs = Ks + 64 * QP;        // [32][VP]  row-pair packed

    const int tid  = threadIdx.x;
    const int wq   = tid >> 5;
    const int lane = tid & 31;
    const int g    = lane >> 2;
    const int tig  = lane & 3;
    const int qt   = gridDim.x - 1 - blockIdx.x;   // long CTAs first
    const int bh   = blockIdx.y;
    const int qi0  = qt * 64;

    const float* Qg = g_Q + (size_t)bh * N_ * DH_;
    const float* Kg = g_K + (size_t)bh * N_ * DH_;
    const float* Vg = g_V + (size_t)bh * N_ * DH_;

    const float qscale = 0.125f * 1.44269504088896340736f; // dh^-0.5 * log2(e)

    // Stage Q (half2 along dh, pre-scaled): 64 rows x 16 float4 = 1024 slots
#pragma unroll
    for (int u = 0; u < 8; u++) {
        int f  = tid + 128 * u;
        int r  = f >> 4;
        int dv = f & 15;
        float4 v = *(const float4*)(Qg + (size_t)(qi0 + r) * DH_ + dv * 4);
        *(uint2*)&Qs[r * QP + dv * 2] =
            make_uint2(h2pack(v.x * qscale, v.y * qscale),
                       h2pack(v.z * qscale, v.w * qscale));
    }

    float m0r = -1e30f, m1r = -1e30f;
    float l0r = 0.f, l1r = 0.f;
    float O[8][4];
#pragma unroll
    for (int j = 0; j < 8; j++)
#pragma unroll
        for (int e = 0; e < 4; e++) O[j][e] = 0.f;

    const int row0 = qi0 + wq * 16 + g;
    const int row1 = row0 + 8;

    for (int kt2 = 0; kt2 <= qt; kt2++) {
        const int kj0 = kt2 * 64;
        __syncthreads();   // previous iteration done with Ks/Vs

        // Stage K (half2 along dh): 1024 float4 slots / 128 thr = 8 iters
#pragma unroll
        for (int u = 0; u < 8; u++) {
            int f  = tid + 128 * u;
            int r  = f >> 4;
            int dv = f & 15;
            float4 kv = *(const float4*)(Kg + (size_t)(kj0 + r) * DH_ + dv * 4);
            *(uint2*)&Ks[r * QP + dv * 2] =
                make_uint2(h2pack(kv.x, kv.y), h2pack(kv.z, kv.w));
        }
        // Stage V row-pair packed: 32 pairs x 16 float4-cols = 512 slots = 4 iters
#pragma unroll
        for (int u = 0; u < 4; u++) {
            int f  = tid + 128 * u;
            int m  = f >> 4;            // row pair 0..31
            int ev = f & 15;            // float4 col group
            float4 v0 = *(const float4*)(Vg + (size_t)(kj0 + 2 * m) * DH_ + ev * 4);
            float4 v1 = *(const float4*)(Vg + (size_t)(kj0 + 2 * m + 1) * DH_ + ev * 4);
            uint4 t;
            t.x = h2pack(v0.x, v1.x);
            t.y = h2pack(v0.y, v1.y);
            t.z = h2pack(v0.z, v1.z);
            t.w = h2pack(v0.w, v1.w);
            *(uint4*)&Vs[m * VP + ev * 4] = t;
        }
        __syncthreads();

        // ---- S = Q @ K^T  (m16 x n64, k=64 via 4 k16-blocks) ----
        float S[8][4];
#pragma unroll
        for (int j = 0; j < 8; j++)
#pragma unroll
            for (int e = 0; e < 4; e++) S[j][e] = 0.f;

#pragma unroll
        for (int kb = 0; kb < 4; kb++) {
            const int ar = (wq * 16 + g) * QP + kb * 8 + tig;
            uint32_t a0 = Qs[ar];
            uint32_t a1 = Qs[ar + 8 * QP];
            uint32_t a2 = Qs[ar + 4];
            uint32_t a3 = Qs[ar + 8 * QP + 4];
#pragma unroll
            for (int j = 0; j < 8; j++) {
                const int br = (j * 8 + g) * QP + kb * 8 + tig;
                uint32_t b0 = Ks[br];
                uint32_t b1 = Ks[br + 4];
                mma_f16_16x8x16(S[j][0], S[j][1], S[j][2], S[j][3],
                                a0, a1, a2, a3, b0, b1);
            }
        }

        // ---- causal mask (diag tile only) ----
        if (kt2 == qt) {
#pragma unroll
            for (int j = 0; j < 8; j++) {
                int c = kj0 + j * 8 + tig * 2;
                if (c     > row0) S[j][0] = -1e30f;
                if (c + 1 > row0) S[j][1] = -1e30f;
                if (c     > row1) S[j][2] = -1e30f;
                if (c + 1 > row1) S[j][3] = -1e30f;
            }
        }

        // ---- online softmax (exp2 domain) ----
        float rmax0 = -1e30f, rmax1 = -1e30f;
#pragma unroll
        for (int j = 0; j < 8; j++) {
            rmax0 = fmaxf(rmax0, fmaxf(S[j][0], S[j][1]));
            rmax1 = fmaxf(rmax1, fmaxf(S[j][2], S[j][3]));
        }
        rmax0 = fmaxf(rmax0, __shfl_xor_sync(0xffffffffu, rmax0, 1));
        rmax0 = fmaxf(rmax0, __shfl_xor_sync(0xffffffffu, rmax0, 2));
        rmax1 = fmaxf(rmax1, __shfl_xor_sync(0xffffffffu, rmax1, 1));
        rmax1 = fmaxf(rmax1, __shfl_xor_sync(0xffffffffu, rmax1, 2));

        float mn0 = fmaxf(m0r, rmax0);
        float mn1 = fmaxf(m1r, rmax1);
        float al0 = ex2f(m0r - mn0);
        float al1 = ex2f(m1r - mn1);
        m0r = mn0; m1r = mn1;

        float sum0 = 0.f, sum1 = 0.f;
        uint32_t ph[8][2];   // [S tile][row-half]: half2 of (col 2tig, 2tig+1)
#pragma unroll
        for (int j = 0; j < 8; j++) {
            float p0 = ex2f(S[j][0] - mn0);
            float p1 = ex2f(S[j][1] - mn0);
            float p2 = ex2f(S[j][2] - mn1);
            float p3 = ex2f(S[j][3] - mn1);
            sum0 += p0 + p1;
            sum1 += p2 + p3;
            ph[j][0] = h2pack(p0, p1);
            ph[j][1] = h2pack(p2, p3);
        }
        sum0 += __shfl_xor_sync(0xffffffffu, sum0, 1);
        sum0 += __shfl_xor_sync(0xffffffffu, sum0, 2);
        sum1 += __shfl_xor_sync(0xffffffffu, sum1, 1);
        sum1 += __shfl_xor_sync(0xffffffffu, sum1, 2);
        l0r = l0r * al0 + sum0;
        l1r = l1r * al1 + sum1;

#pragma unroll
        for (int j = 0; j < 8; j++) {
            O[j][0] *= al0; O[j][1] *= al0;
            O[j][2] *= al1; O[j][3] *= al1;
        }

        // ---- O += P @ V (shuffle-free: ph IS the m16n8k16 A fragment) ----
#pragma unroll
        for (int kb = 0; kb < 4; kb++) {
            uint32_t a0 = ph[2 * kb][0];
            uint32_t a1 = ph[2 * kb][1];
            uint32_t a2 = ph[2 * kb + 1][0];
            uint32_t a3 = ph[2 * kb + 1][1];
#pragma unroll
            for (int j = 0; j < 8; j++) {
                uint32_t b0 = Vs[(kb * 8 + tig) * VP + j * 8 + g];
                uint32_t b1 = Vs[(kb * 8 + 4 + tig) * VP + j * 8 + g];
                mma_f16_16x8x16(O[j][0], O[j][1], O[j][2], O[j][3],
                                a0, a1, a2, a3, b0, b1);
            }
        }
    }

    // Epilogue: O /= l; write to g_X[b][n][h*64 + e]
    const int b = bh >> 4;
    const int h = bh & 15;
    const float il0 = 1.f / l0r;
    const float il1 = 1.f / l1r;
    float* X0 = g_X + ((size_t)b * N_ + row0) * D_ + h * DH_;
    float* X1 = g_X + ((size_t)b * N_ + row1) * D_ + h * DH_;
#pragma unroll
    for (int j = 0; j < 8; j++) {
        int e = j * 8 + tig * 2;
        *(float2*)(X0 + e) = make_float2(O[j][0] * il0, O[j][1] * il0);
        *(float2*)(X1 + e) = make_float2(O[j][2] * il1, O[j][3] * il1);
    }
}

// ---------------------------------------------------------------------------
extern "C" void kernel_launch(void* const* d_in, const int* in_sizes, int n_in,
                              void* d_out, int out_size)
{
    const float* q  = (const float*)d_in[0];
    const float* k  = (const float*)d_in[1];
    const float* v  = (const float*)d_in[2];
    const float* Wq = (const float*)d_in[3];
    const float* bq = (const float*)d_in[4];
    const float* Wk = (const float*)d_in[5];
    const float* bk = (const float*)d_in[6];
    const float* Wv = (const float*)d_in[7];
    const float* bv = (const float*)d_in[8];
    const float* Wo = (const float*)d_in[9];
    float* out = (float*)d_out;

    cudaFuncSetAttribute(flash_mma_kernel, cudaFuncAttributeMaxDynamicSharedMemorySize,
                         FL_SMEM);

    // QKV projections: M=8192 -> 64 row-tiles, N=1024 -> 8 col-tiles, z = q/k/v
    dim3 gp(8, 64, 3);
    proj_qkv_mma<<<gp, 256>>>(q, k, v, Wq, bq, Wk, bk, Wv, bv);

    // Flash attention: 32 q-tiles x 64 (b,h) pairs
    dim3 gf(N_ / 64, B_ * H_);
    flash_mma_kernel<<<gf, 128, FL_SMEM>>>();

    // Output projection
    dim3 go(8, 64, 1);
    proj_out_mma<<<go, 256>>>(Wo, out);
}